// round 15
// baseline (speedup 1.0000x reference)
#include <cuda_runtime.h>

#define HH 50
#define TT 96
#define NPRED 12
#define NTH 128   // 4 warps: unit 0 (warps 0-1) = I,F gates; unit 1 (warps 2-3) = G,O + state
#define EPB 2     // batch elements per block

typedef unsigned long long u64;

__device__ __forceinline__ u64 pk2(float lo, float hi) {
    u64 r; asm("mov.b64 %0, {%1,%2};" : "=l"(r) : "f"(lo), "f"(hi)); return r;
}
__device__ __forceinline__ void upk2(u64 v, float &lo, float &hi) {
    asm("mov.b64 {%0,%1}, %2;" : "=f"(lo), "=f"(hi) : "l"(v));
}
__device__ __forceinline__ u64 ffma2(u64 a, u64 b, u64 c) {
    u64 d; asm("fma.rn.f32x2 %0, %1, %2, %3;" : "=l"(d) : "l"(a), "l"(b), "l"(c)); return d;
}
__device__ __forceinline__ float ftanh(float x) {
    float y; asm("tanh.approx.f32 %0, %1;" : "=f"(y) : "f"(x)); return y;
}

__global__ __launch_bounds__(NTH, 4)
void lstm_recursive_kernel(const float* __restrict__ x,
                           const float* __restrict__ W_ih,
                           const float* __restrict__ W_hh,
                           const float* __restrict__ b_ih,
                           const float* __restrict__ b_hh,
                           const float* __restrict__ W_fc,
                           const float* __restrict__ b_fc,
                           float* __restrict__ out) {
    const int unit = threadIdx.x >> 6;             // 0 = IF, 1 = GO
    const int j    = threadIdx.x & 63;
    const int jr   = (j < HH) ? j : (HH - 1);      // clamped row
    const int b0   = blockIdx.x * EPB;

    __shared__ __align__(16) float sh[EPB][2][64];   // h, double-buffered, padded
    __shared__ __align__(8)  float2 sgate[EPB][64];  // activated (i_, f_) per elem/row
    __shared__ float swin[EPB][TT + NPRED];
    __shared__ float sred[EPB][64];

    for (int i = threadIdx.x; i < EPB * TT; i += NTH)
        swin[i / TT][i % TT] = x[(b0 + i / TT) * TT + (i % TT)];

    // Unit's 2 gate rows. IF: gates 0,1 (i,f) — sigmoid, 0.5-prescaled.
    //                     GO: gates 2,3 (g,o) — g raw (tanh), o 0.5-prescaled.
    const int gA = unit ? 2 : 0;
    const int gB = unit ? 3 : 1;
    const float sA = unit ? 1.0f : 0.5f;           // prescale for first gate
    const float sB = 0.5f;                          // f and o are both sigmoid
    u64 wX[25], wY[25];                             // 100 regs of packed K-pairs
    {
        const float2* rX = (const float2*)(W_hh + (gA * HH + jr) * HH);
        const float2* rY = (const float2*)(W_hh + (gB * HH + jr) * HH);
#pragma unroll
        for (int k = 0; k < 25; k++) {
            float2 vx = rX[k], vy = rY[k];
            wX[k] = pk2(sA * vx.x, sA * vx.y);
            wY[k] = pk2(sB * vy.x, sB * vy.y);
        }
    }
    const float xwX = sA * W_ih[gA * HH + jr];
    const float xwY = sB * W_ih[gB * HH + jr];
    const float bX  = sA * (b_ih[gA * HH + jr] + b_hh[gA * HH + jr]);
    const float bY  = sB * (b_ih[gB * HH + jr] + b_hh[gB * HH + jr]);
    const float wfc = (j < HH) ? W_fc[jr] : 0.0f;
    const float bfc = b_fc[0];

    for (int p = 0; p < NPRED; p++) {
        // zero h buffers: unit 0 covers elem 0, unit 1 covers elem 1
        sh[unit][0][j] = 0.0f;
        sh[unit][1][j] = 0.0f;
        float cA = 0.0f, cB = 0.0f, hnA = 0.0f, hnB = 0.0f;   // GO-unit state
        __syncthreads();

#pragma unroll 1
        for (int t = 0; t < TT; t++) {
            const int buf = t & 1;
            // ---- matvec: 2 gates x 2 elements = 4 FFMA2 chains (100 FFMA2) ----
            const float xtA = swin[0][p + t];
            const float xtB = swin[1][p + t];
            u64 aXA = pk2(fmaf(xtA, xwX, bX), 0.0f);
            u64 aYA = pk2(fmaf(xtA, xwY, bY), 0.0f);
            u64 aXB = pk2(fmaf(xtB, xwX, bX), 0.0f);
            u64 aYB = pk2(fmaf(xtB, xwY, bY), 0.0f);
            const ulonglong2* h0 = (const ulonglong2*)sh[0][buf];
            const ulonglong2* h1 = (const ulonglong2*)sh[1][buf];
#pragma unroll
            for (int cc = 0; cc < 12; cc++) {
                ulonglong2 hvA = h0[cc];
                ulonglong2 hvB = h1[cc];
                aXA = ffma2(wX[2 * cc], hvA.x, aXA);
                aYA = ffma2(wY[2 * cc], hvA.x, aYA);
                aXB = ffma2(wX[2 * cc], hvB.x, aXB);
                aYB = ffma2(wY[2 * cc], hvB.x, aYB);
                aXA = ffma2(wX[2 * cc + 1], hvA.y, aXA);
                aYA = ffma2(wY[2 * cc + 1], hvA.y, aYA);
                aXB = ffma2(wX[2 * cc + 1], hvB.y, aXB);
                aYB = ffma2(wY[2 * cc + 1], hvB.y, aYB);
            }
            {   // k = 48,49
                u64 htA = ((const u64*)sh[0][buf])[24];
                u64 htB = ((const u64*)sh[1][buf])[24];
                aXA = ffma2(wX[24], htA, aXA);
                aYA = ffma2(wY[24], htA, aYA);
                aXB = ffma2(wX[24], htB, aXB);
                aYB = ffma2(wY[24], htB, aYB);
            }
            float zXA, zXA2, zYA, zYA2, zXB, zXB2, zYB, zYB2;
            upk2(aXA, zXA, zXA2);
            upk2(aYA, zYA, zYA2);
            upk2(aXB, zXB, zXB2);
            upk2(aYB, zYB, zYB2);
            const float vXA = zXA + zXA2;          // gate gA, elem A (prescaled)
            const float vYA = zYA + zYA2;          // gate gB, elem A
            const float vXB = zXB + zXB2;
            const float vYB = zYB + zYB2;

            if (unit == 0) {
                // IF-unit: activate sigmoids, export (i_, f_)
                float2 ga, gb;
                ga.x = fmaf(0.5f, ftanh(vXA), 0.5f);   // i_A
                ga.y = fmaf(0.5f, ftanh(vYA), 0.5f);   // f_A
                gb.x = fmaf(0.5f, ftanh(vXB), 0.5f);   // i_B
                gb.y = fmaf(0.5f, ftanh(vYB), 0.5f);   // f_B
                sgate[0][j] = ga;
                sgate[1][j] = gb;
            }
            __syncthreads();                        // gates visible to GO
            if (unit == 1) {
                const float2 ga = sgate[0][jr];     // (i_A, f_A)
                const float2 gb = sgate[1][jr];
                const float g_A = ftanh(vXA);
                const float o_A = fmaf(0.5f, ftanh(vYA), 0.5f);
                const float g_B = ftanh(vXB);
                const float o_B = fmaf(0.5f, ftanh(vYB), 0.5f);
                cA  = fmaf(ga.y, cA, ga.x * g_A);
                hnA = o_A * ftanh(cA);
                cB  = fmaf(gb.y, cB, gb.x * g_B);
                hnB = o_B * ftanh(cB);
                sh[0][buf ^ 1][j] = hnA;
                sh[1][buf ^ 1][j] = hnB;
            }
            __syncthreads();                        // new h visible for next step
        }

        // FC head (GO-unit owns h)
        if (unit == 1) {
            sred[0][j] = hnA * wfc;
            sred[1][j] = hnB * wfc;
        }
        __syncthreads();
        if (unit == 1 && j < EPB) {
            float s = bfc;
#pragma unroll
            for (int k = 0; k < HH; k++) s += sred[j][k];
            swin[j][TT + p] = s;
            out[(b0 + j) * NPRED + p] = s;
        }
        __syncthreads();
    }
}

extern "C" void kernel_launch(void* const* d_in, const int* in_sizes, int n_in,
                              void* d_out, int out_size) {
    const float* x    = (const float*)d_in[0];
    const float* W_ih = (const float*)d_in[1];
    const float* W_hh = (const float*)d_in[2];
    const float* b_ih = (const float*)d_in[3];
    const float* b_hh = (const float*)d_in[4];
    const float* W_fc = (const float*)d_in[5];
    const float* b_fc = (const float*)d_in[6];
    float* out = (float*)d_out;

    const int B = out_size / NPRED;               // 1024
    lstm_recursive_kernel<<<B / EPB, NTH>>>(x, W_ih, W_hh, b_ih, b_hh, W_fc, b_fc, out);
}

// round 16
// speedup vs baseline: 1.3563x; 1.3563x over previous
#include <cuda_runtime.h>

#define HH 50
#define TT 96
#define NPRED 12
#define NTH 64
#define EPB 2
#define BTOT 1024

typedef unsigned long long u64;

// scratch: per-chain (p, b) final prefix state
__device__ float g_hs[NPRED * BTOT * HH];
__device__ float g_cs[NPRED * BTOT * HH];

__device__ __forceinline__ u64 pk2(float lo, float hi) {
    u64 r; asm("mov.b64 %0, {%1,%2};" : "=l"(r) : "f"(lo), "f"(hi)); return r;
}
__device__ __forceinline__ void upk2(u64 v, float &lo, float &hi) {
    asm("mov.b64 {%0,%1}, %2;" : "=f"(lo), "=f"(hi) : "l"(v));
}
__device__ __forceinline__ u64 ffma2(u64 a, u64 b, u64 c) {
    u64 d; asm("fma.rn.f32x2 %0, %1, %2, %3;" : "=l"(d) : "l"(a), "l"(b), "l"(c)); return d;
}
__device__ __forceinline__ float ftanh(float x) {
    float y; asm("tanh.approx.f32 %0, %1;" : "=f"(y) : "f"(x)); return y;
}
__device__ __forceinline__ float fsig(float x) {
    return fmaf(0.5f, ftanh(0.5f * x), 0.5f);
}

// load the R10 weight set (shared helper)
struct WReg {
    u64 w[4][25];
    float wih[4], bsum[4];
};
__device__ __forceinline__ void load_weights(WReg &W, int jr,
                                             const float* __restrict__ W_ih,
                                             const float* __restrict__ W_hh,
                                             const float* __restrict__ b_ih,
                                             const float* __restrict__ b_hh) {
#pragma unroll
    for (int g = 0; g < 4; g++) {
        const int row = g * HH + jr;
        const float2* wr = (const float2*)(W_hh + row * HH);
#pragma unroll
        for (int k = 0; k < 25; k++) {
            float2 v = wr[k];
            W.w[g][k] = pk2(v.x, v.y);
        }
        W.wih[g]  = W_ih[row];
        W.bsum[g] = b_ih[row] + b_hh[row];
    }
}

// ============ K1: all 12x1024 prefix chains in parallel ============
__global__ __launch_bounds__(NTH)
void lstm_prefix_kernel(const float* __restrict__ x,
                        const float* __restrict__ W_ih,
                        const float* __restrict__ W_hh,
                        const float* __restrict__ b_ih,
                        const float* __restrict__ b_hh) {
    const int j  = threadIdx.x;
    const int jr = (j < HH) ? j : (HH - 1);
    const int p    = blockIdx.x / (BTOT / EPB);    // run index 0..11
    const int pair = blockIdx.x % (BTOT / EPB);
    const int b0   = pair * EPB;
    const int TTp  = TT - p;                        // prefix length

    __shared__ __align__(16) float sh[EPB][2][64];
    __shared__ float swin[EPB][TT];

#pragma unroll
    for (int e = 0; e < EPB; e++)
        for (int i = j; i < TTp; i += NTH) swin[e][i] = x[(b0 + e) * TT + p + i];

    WReg W;
    load_weights(W, jr, W_ih, W_hh, b_ih, b_hh);

#pragma unroll
    for (int e = 0; e < EPB; e++) { sh[e][0][j] = 0.0f; sh[e][1][j] = 0.0f; }
    float c[EPB], hnew[EPB];
#pragma unroll
    for (int e = 0; e < EPB; e++) { c[e] = 0.0f; hnew[e] = 0.0f; }
    __syncthreads();

#pragma unroll 1
    for (int t = 0; t < TTp; t++) {
        const int buf = t & 1;
        u64 a0[EPB], a1[EPB], a2[EPB], a3[EPB];
#pragma unroll
        for (int e = 0; e < EPB; e++) {
            const float xt = swin[e][t];
            a0[e] = pk2(fmaf(xt, W.wih[0], W.bsum[0]), 0.0f);
            a1[e] = pk2(fmaf(xt, W.wih[1], W.bsum[1]), 0.0f);
            a2[e] = pk2(fmaf(xt, W.wih[2], W.bsum[2]), 0.0f);
            a3[e] = pk2(fmaf(xt, W.wih[3], W.bsum[3]), 0.0f);
        }
        const ulonglong2* h0 = (const ulonglong2*)sh[0][buf];
        const ulonglong2* h1 = (const ulonglong2*)sh[1][buf];
#pragma unroll
        for (int cc = 0; cc < 12; cc++) {
            ulonglong2 hvA = h0[cc];
            ulonglong2 hvB = h1[cc];
            a0[0] = ffma2(W.w[0][2 * cc], hvA.x, a0[0]);
            a1[0] = ffma2(W.w[1][2 * cc], hvA.x, a1[0]);
            a2[0] = ffma2(W.w[2][2 * cc], hvA.x, a2[0]);
            a3[0] = ffma2(W.w[3][2 * cc], hvA.x, a3[0]);
            a0[1] = ffma2(W.w[0][2 * cc], hvB.x, a0[1]);
            a1[1] = ffma2(W.w[1][2 * cc], hvB.x, a1[1]);
            a2[1] = ffma2(W.w[2][2 * cc], hvB.x, a2[1]);
            a3[1] = ffma2(W.w[3][2 * cc], hvB.x, a3[1]);
            a0[0] = ffma2(W.w[0][2 * cc + 1], hvA.y, a0[0]);
            a1[0] = ffma2(W.w[1][2 * cc + 1], hvA.y, a1[0]);
            a2[0] = ffma2(W.w[2][2 * cc + 1], hvA.y, a2[0]);
            a3[0] = ffma2(W.w[3][2 * cc + 1], hvA.y, a3[0]);
            a0[1] = ffma2(W.w[0][2 * cc + 1], hvB.y, a0[1]);
            a1[1] = ffma2(W.w[1][2 * cc + 1], hvB.y, a1[1]);
            a2[1] = ffma2(W.w[2][2 * cc + 1], hvB.y, a2[1]);
            a3[1] = ffma2(W.w[3][2 * cc + 1], hvB.y, a3[1]);
        }
        {
            u64 htA = ((const u64*)sh[0][buf])[24];
            u64 htB = ((const u64*)sh[1][buf])[24];
            a0[0] = ffma2(W.w[0][24], htA, a0[0]);
            a1[0] = ffma2(W.w[1][24], htA, a1[0]);
            a2[0] = ffma2(W.w[2][24], htA, a2[0]);
            a3[0] = ffma2(W.w[3][24], htA, a3[0]);
            a0[1] = ffma2(W.w[0][24], htB, a0[1]);
            a1[1] = ffma2(W.w[1][24], htB, a1[1]);
            a2[1] = ffma2(W.w[2][24], htB, a2[1]);
            a3[1] = ffma2(W.w[3][24], htB, a3[1]);
        }
#pragma unroll
        for (int e = 0; e < EPB; e++) {
            float l0, hi0, l1, hi1, l2, hi2, l3, hi3;
            upk2(a0[e], l0, hi0);
            upk2(a1[e], l1, hi1);
            upk2(a2[e], l2, hi2);
            upk2(a3[e], l3, hi3);
            const float i_ = fsig(l0 + hi0);
            const float f_ = fsig(l1 + hi1);
            const float g_ = ftanh(l2 + hi2);
            const float o_ = fsig(l3 + hi3);
            c[e]    = fmaf(f_, c[e], i_ * g_);
            hnew[e] = o_ * ftanh(c[e]);
            sh[e][buf ^ 1][j] = hnew[e];
        }
        __syncthreads();
    }

    if (j < HH) {
#pragma unroll
        for (int e = 0; e < EPB; e++) {
            const int chain = p * BTOT + b0 + e;
            g_hs[chain * HH + j] = hnew[e];
            g_cs[chain * HH + j] = c[e];
        }
    }
}

// ============ K2: sequential suffix (66 short steps per batch element) ============
__global__ __launch_bounds__(NTH)
void lstm_suffix_kernel(const float* __restrict__ W_ih,
                        const float* __restrict__ W_hh,
                        const float* __restrict__ b_ih,
                        const float* __restrict__ b_hh,
                        const float* __restrict__ W_fc,
                        const float* __restrict__ b_fc,
                        float* __restrict__ out) {
    const int j  = threadIdx.x;
    const int jr = (j < HH) ? j : (HH - 1);
    const int b  = blockIdx.x;

    __shared__ __align__(16) float hq[NPRED][64];   // run states (rows 16B aligned)
    __shared__ float sred[64];
    __shared__ float spred;

    float cr[NPRED];
#pragma unroll
    for (int p = 0; p < NPRED; p++) {
        const int chain = p * BTOT + b;
        hq[p][j] = (j < HH) ? g_hs[chain * HH + j] : 0.0f;
        cr[p]    = g_cs[chain * HH + jr];            // pads duplicate row 49 (unused)
    }

    WReg W;
    load_weights(W, jr, W_ih, W_hh, b_ih, b_hh);
    const float wfc = (j < HH) ? W_fc[jr] : 0.0f;
    const float bfc = b_fc[0];
    __syncthreads();

#pragma unroll 1
    for (int q = 0; q < NPRED; q++) {
        // pred_q = FC(hq[q])
        sred[j] = hq[q][jr] * wfc;
        __syncthreads();
        if (j == 0) {
            float s = bfc;
#pragma unroll
            for (int k = 0; k < HH; k++) s += sred[k];
            spred = s;
            out[b * NPRED + q] = s;
        }
        __syncthreads();
        const float xt = spred;

        // advance runs p > q by one step with input xt
#pragma unroll 1
        for (int p = q + 1; p < NPRED; p++) {
            u64 a0, a1, a2, a3;
            a0 = pk2(fmaf(xt, W.wih[0], W.bsum[0]), 0.0f);
            a1 = pk2(fmaf(xt, W.wih[1], W.bsum[1]), 0.0f);
            a2 = pk2(fmaf(xt, W.wih[2], W.bsum[2]), 0.0f);
            a3 = pk2(fmaf(xt, W.wih[3], W.bsum[3]), 0.0f);
            const ulonglong2* hv = (const ulonglong2*)hq[p];
#pragma unroll
            for (int cc = 0; cc < 12; cc++) {
                ulonglong2 h4 = hv[cc];
                a0 = ffma2(W.w[0][2 * cc], h4.x, a0);
                a1 = ffma2(W.w[1][2 * cc], h4.x, a1);
                a2 = ffma2(W.w[2][2 * cc], h4.x, a2);
                a3 = ffma2(W.w[3][2 * cc], h4.x, a3);
                a0 = ffma2(W.w[0][2 * cc + 1], h4.y, a0);
                a1 = ffma2(W.w[1][2 * cc + 1], h4.y, a1);
                a2 = ffma2(W.w[2][2 * cc + 1], h4.y, a2);
                a3 = ffma2(W.w[3][2 * cc + 1], h4.y, a3);
            }
            {
                u64 ht = ((const u64*)hq[p])[24];
                a0 = ffma2(W.w[0][24], ht, a0);
                a1 = ffma2(W.w[1][24], ht, a1);
                a2 = ffma2(W.w[2][24], ht, a2);
                a3 = ffma2(W.w[3][24], ht, a3);
            }
            __syncthreads();                         // all reads of hq[p] done
            float l0, hi0, l1, hi1, l2, hi2, l3, hi3;
            upk2(a0, l0, hi0);
            upk2(a1, l1, hi1);
            upk2(a2, l2, hi2);
            upk2(a3, l3, hi3);
            const float i_ = fsig(l0 + hi0);
            const float f_ = fsig(l1 + hi1);
            const float g_ = ftanh(l2 + hi2);
            const float o_ = fsig(l3 + hi3);
            cr[p] = fmaf(f_, cr[p], i_ * g_);
            const float hn = o_ * ftanh(cr[p]);
            hq[p][j] = (j < HH) ? hn : 0.0f;
            __syncthreads();                         // writes visible
        }
    }
}

extern "C" void kernel_launch(void* const* d_in, const int* in_sizes, int n_in,
                              void* d_out, int out_size) {
    const float* x    = (const float*)d_in[0];
    const float* W_ih = (const float*)d_in[1];
    const float* W_hh = (const float*)d_in[2];
    const float* b_ih = (const float*)d_in[3];
    const float* b_hh = (const float*)d_in[4];
    const float* W_fc = (const float*)d_in[5];
    const float* b_fc = (const float*)d_in[6];
    float* out = (float*)d_out;

    lstm_prefix_kernel<<<NPRED * (BTOT / EPB), NTH>>>(x, W_ih, W_hh, b_ih, b_hh);
    lstm_suffix_kernel<<<BTOT, NTH>>>(W_ih, W_hh, b_ih, b_hh, W_fc, b_fc, out);
}